// round 16
// baseline (speedup 1.0000x reference)
#include <cuda_runtime.h>
#include <cuda_bf16.h>
#include <cstdint>

#define NN 16384
#define EE 524288
#define BG 8
#define FIN 26
#define DD 128
#define HH 256
#define NOUT 64
#define NL 4
#define NRBF 16

// ---------------- device scratch (statically allocated; no cudaMalloc) -------
__device__ float g_h[NN * DD];        // node features (residual stream)
__device__ float g_P[NN * HH];        // h @ W1a + b1
__device__ float g_Q[NN * HH];        // h @ W1b
__device__ float g_ef[EE * NRBF];     // edge RBF features (valid only if flag)
__device__ int   g_eflag[EE];         // 1 if d < cutoff (ef nonzero)
__device__ float g_S[NN * HH];        // sum of silu(z) per dst node
__device__ float g_degf[NN];          // per-node in-degree (float)
__device__ float g_gsum[BG * DD];     // per-graph sums
// pre-split bf16 weights (hi/lo Markidis pairs)
__device__ __nv_bfloat16 g_Wpq_h[NL * 128 * 512];  // [W1a|W1b] concat on N
__device__ __nv_bfloat16 g_Wpq_l[NL * 128 * 512];
__device__ __nv_bfloat16 g_uW1h[NL * HH * HH];
__device__ __nv_bfloat16 g_uW1l[NL * HH * HH];
__device__ __nv_bfloat16 g_uW2h[NL * HH * DD];
__device__ __nv_bfloat16 g_uW2l[NL * HH * DD];
__device__ __nv_bfloat16 g_mW2h[NL * HH * DD];
__device__ __nv_bfloat16 g_mW2l[NL * HH * DD];

__device__ __forceinline__ float silu_f(float x) {
    return x * __frcp_rn(1.f + __expf(-x));
}

__device__ __forceinline__ void red_v4(float* p, float a, float b, float c, float d) {
    asm volatile("red.global.add.v4.f32 [%0], {%1,%2,%3,%4};"
                 :: "l"(p), "f"(a), "f"(b), "f"(c), "f"(d) : "memory");
}

// ---------------- mma.sync helpers ------------------------------------------
__device__ __forceinline__ uint32_t smem_u32(const void* p) {
    return (uint32_t)__cvta_generic_to_shared(p);
}
__device__ __forceinline__ void ldsm_x4(uint32_t& r0, uint32_t& r1,
                                        uint32_t& r2, uint32_t& r3, uint32_t a) {
    asm volatile("ldmatrix.sync.aligned.m8n8.x4.shared.b16 {%0,%1,%2,%3}, [%4];"
                 : "=r"(r0), "=r"(r1), "=r"(r2), "=r"(r3) : "r"(a));
}
__device__ __forceinline__ void ldsm_x4_t(uint32_t& r0, uint32_t& r1,
                                          uint32_t& r2, uint32_t& r3, uint32_t a) {
    asm volatile("ldmatrix.sync.aligned.m8n8.x4.trans.shared.b16 {%0,%1,%2,%3}, [%4];"
                 : "=r"(r0), "=r"(r1), "=r"(r2), "=r"(r3) : "r"(a));
}
__device__ __forceinline__ void mma_bf16(float* d, uint32_t a0, uint32_t a1,
                                         uint32_t a2, uint32_t a3,
                                         uint32_t b0, uint32_t b1) {
    asm volatile(
        "mma.sync.aligned.m16n8k16.row.col.f32.bf16.bf16.f32 "
        "{%0,%1,%2,%3}, {%4,%5,%6,%7}, {%8,%9}, {%0,%1,%2,%3};"
        : "+f"(d[0]), "+f"(d[1]), "+f"(d[2]), "+f"(d[3])
        : "r"(a0), "r"(a1), "r"(a2), "r"(a3), "r"(b0), "r"(b1));
}
// pack two floats into (hi-u32, lo-u32) bf16x2 Markidis pairs
__device__ __forceinline__ void split2(float f0, float f1, uint32_t& hi, uint32_t& lo) {
    __nv_bfloat16 h0 = __float2bfloat16_rn(f0);
    __nv_bfloat16 h1 = __float2bfloat16_rn(f1);
    __nv_bfloat16 l0 = __float2bfloat16_rn(f0 - __bfloat162float(h0));
    __nv_bfloat16 l1 = __float2bfloat16_rn(f1 - __bfloat162float(h1));
    hi = (uint32_t)__bfloat16_as_ushort(h0) | ((uint32_t)__bfloat16_as_ushort(h1) << 16);
    lo = (uint32_t)__bfloat16_as_ushort(l0) | ((uint32_t)__bfloat16_as_ushort(l1) << 16);
}

// ---------------- weight pre-split kernels -----------------------------------
__global__ void __launch_bounds__(256) split_wpq_kernel(const float* __restrict__ mW1)
{
    int i = blockIdx.x * blockDim.x + threadIdx.x;
    if (i >= NL * 128 * 512) return;
    int l = i / (128 * 512);
    int r = i % (128 * 512);
    int k = r / 512, n = r % 512;
    float w = (n < 256) ? mW1[(size_t)(l * 272 + k) * HH + n]
                        : mW1[(size_t)(l * 272 + 128 + k) * HH + (n - 256)];
    __nv_bfloat16 wh = __float2bfloat16_rn(w);
    g_Wpq_h[i] = wh;
    g_Wpq_l[i] = __float2bfloat16_rn(w - __bfloat162float(wh));
}
__global__ void __launch_bounds__(256) split_uw_kernel(
    const float* __restrict__ uW1, const float* __restrict__ uW2,
    const float* __restrict__ mW2)
{
    int i = blockIdx.x * blockDim.x + threadIdx.x;
    if (i < NL * HH * HH) {
        float w = uW1[i];
        __nv_bfloat16 wh = __float2bfloat16_rn(w);
        g_uW1h[i] = wh;
        g_uW1l[i] = __float2bfloat16_rn(w - __bfloat162float(wh));
    }
    if (i < NL * HH * DD) {
        float w = uW2[i];
        __nv_bfloat16 wh = __float2bfloat16_rn(w);
        g_uW2h[i] = wh;
        g_uW2l[i] = __float2bfloat16_rn(w - __bfloat162float(wh));
        float m = mW2[i];
        __nv_bfloat16 mh = __float2bfloat16_rn(m);
        g_mW2h[i] = mh;
        g_mW2l[i] = __float2bfloat16_rn(m - __bfloat162float(mh));
    }
}

// ---------------- embedding MLP: 26 -> 128 -> silu -> 128 -------------------
__global__ void __launch_bounds__(128) embed_kernel(
    const float* __restrict__ x, const float* __restrict__ W1,
    const float* __restrict__ b1, const float* __restrict__ W2,
    const float* __restrict__ b2)
{
    __shared__ float xs[4][FIN];
    __shared__ float hid[4][DD];
    int t = threadIdx.x;
    int n0 = blockIdx.x * 4;
    for (int i = t; i < 4 * FIN; i += 128)
        xs[i / FIN][i % FIN] = x[(size_t)n0 * FIN + i];
    __syncthreads();
    float b1t = b1[t];
    #pragma unroll
    for (int nd = 0; nd < 4; nd++) {
        float acc = b1t;
        #pragma unroll
        for (int k = 0; k < FIN; k++) acc += xs[nd][k] * W1[k * DD + t];
        hid[nd][t] = silu_f(acc);
    }
    __syncthreads();
    float b2t = b2[t];
    #pragma unroll
    for (int nd = 0; nd < 4; nd++) {
        float acc = b2t;
        for (int k = 0; k < DD; k++) acc += hid[nd][k] * W2[k * DD + t];
        g_h[(size_t)(n0 + nd) * DD + t] = acc;
    }
}

// ---------------- edge RBF + cutoff flag (skip stores when out of cutoff) ----
__global__ void __launch_bounds__(256) rbf_kernel(
    const float* __restrict__ pos, const int* __restrict__ ei)
{
    int e = blockIdx.x * blockDim.x + threadIdx.x;
    if (e >= EE) return;
    int s  = ei[e];
    int dd = ei[EE + e];
    float dx = pos[dd * 3 + 0] - pos[s * 3 + 0];
    float dy = pos[dd * 3 + 1] - pos[s * 3 + 1];
    float dz = pos[dd * 3 + 2] - pos[s * 3 + 2];
    float d = sqrtf(dx * dx + dy * dy + dz * dz + 1e-12f);
    bool in_cut = (d < 10.f);
    g_eflag[e] = in_cut ? 1 : 0;
    if (!in_cut) return;   // ef never read for these edges
    float env = 0.5f * (cosf(0.31415926535897932f * d) + 1.f);
    #pragma unroll
    for (int i = 0; i < NRBF; i++) {
        float c = (10.f / 15.f) * (float)i;
        float u = d - c;
        g_ef[(size_t)e * NRBF + i] = env * __expf(-u * u * 1.28f);
    }
}

// ---------------- degree count -----------------------------------------------
__global__ void __launch_bounds__(256) zero_deg_kernel()
{
    int i = blockIdx.x * blockDim.x + threadIdx.x;
    if (i < NN) g_degf[i] = 0.f;
}
__global__ void __launch_bounds__(256) deg_kernel(const int* __restrict__ ei)
{
    int e = blockIdx.x * blockDim.x + threadIdx.x;
    if (e < EE) atomicAdd(&g_degf[ei[EE + e]], 1.f);
}

// ---------------- pq (tensor-core): [P|Q][64][512] = h[64][128] @ Wpq --------
#define PQ_A_LD 136
#define PQ_W_LD 136
#define PQ_SMEM (64 * PQ_A_LD * 2 * 2 + 64 * PQ_W_LD * 2 * 2)   // 69632 B

__global__ void __launch_bounds__(256) pq_mma_kernel(const float* __restrict__ b1, int l)
{
    extern __shared__ char smc[];
    __nv_bfloat16* Ah = (__nv_bfloat16*)smc;                       // 64*136
    __nv_bfloat16* Al = (__nv_bfloat16*)(smc + 64 * PQ_A_LD * 2);
    __nv_bfloat16* Wh = (__nv_bfloat16*)(smc + 64 * PQ_A_LD * 4);
    __nv_bfloat16* Wl = (__nv_bfloat16*)(smc + 64 * PQ_A_LD * 4 + 64 * PQ_W_LD * 2);

    int t = threadIdx.x;
    int warp = t >> 5, lane = t & 31;
    int mw = warp & 3, nw = warp >> 2;
    int n0 = blockIdx.x * 64;

    // load h[64][128] fp32 -> split bf16 hi/lo
    const float4* hp = (const float4*)(g_h + (size_t)n0 * DD);
    #pragma unroll
    for (int j = 0; j < 8; j++) {
        int i = t + j * 256;           // 2048 float4
        int node = i >> 5;
        int k4 = (i & 31) << 2;
        float4 v = hp[i];
        uint32_t h01, l01, h23, l23;
        split2(v.x, v.y, h01, l01);
        split2(v.z, v.w, h23, l23);
        *(uint32_t*)(Ah + node * PQ_A_LD + k4)     = h01;
        *(uint32_t*)(Ah + node * PQ_A_LD + k4 + 2) = h23;
        *(uint32_t*)(Al + node * PQ_A_LD + k4)     = l01;
        *(uint32_t*)(Al + node * PQ_A_LD + k4 + 2) = l23;
    }

    uint32_t a_row = (uint32_t)(mw * 16 + (lane & 15));
    uint32_t a_kh  = (uint32_t)((lane >> 4) << 3);
    uint32_t ah_base = smem_u32(Ah), al_base = smem_u32(Al);
    uint32_t b_krow = (uint32_t)(lane & 15);
    uint32_t b_noff = (uint32_t)(nw * 64 + ((lane >> 4) << 3));
    uint32_t wh_base = smem_u32(Wh), wl_base = smem_u32(Wl);

    const __nv_bfloat16* wpqh = g_Wpq_h + (size_t)l * 128 * 512;
    const __nv_bfloat16* wpql = g_Wpq_l + (size_t)l * 128 * 512;

    int r0 = mw * 16 + (lane >> 2);
    int r1 = r0 + 8;

    for (int nc = 0; nc < 512; nc += 128) {
        float acc[8][4];
        #pragma unroll
        for (int n = 0; n < 8; n++)
            #pragma unroll
            for (int c = 0; c < 4; c++) acc[n][c] = 0.f;

        for (int kc = 0; kc < 128; kc += 64) {
            __syncthreads();
            #pragma unroll
            for (int j = 0; j < 8; j++) {
                int i = t + j * 256;       // 2048 uint2 over [64][128]
                int kk = i >> 5;
                int n4 = (i & 31) << 2;
                *(uint2*)(Wh + kk * PQ_W_LD + n4) =
                    *(const uint2*)(wpqh + (size_t)(kc + kk) * 512 + nc + n4);
                *(uint2*)(Wl + kk * PQ_W_LD + n4) =
                    *(const uint2*)(wpql + (size_t)(kc + kk) * 512 + nc + n4);
            }
            __syncthreads();

            #pragma unroll
            for (int ks = 0; ks < 4; ks++) {
                uint32_t k = (uint32_t)(kc + ks * 16);
                uint32_t ah0, ah1, ah2, ah3, al0, al1, al2, al3;
                ldsm_x4(ah0, ah1, ah2, ah3, ah_base + (a_row * PQ_A_LD + k + a_kh) * 2);
                ldsm_x4(al0, al1, al2, al3, al_base + (a_row * PQ_A_LD + k + a_kh) * 2);
                #pragma unroll
                for (int np = 0; np < 4; np++) {
                    uint32_t off = (((uint32_t)(ks * 16) + b_krow) * PQ_W_LD
                                    + b_noff + (uint32_t)(np * 16)) * 2;
                    uint32_t bh0, bh1, bh2, bh3, bl0, bl1, bl2, bl3;
                    ldsm_x4_t(bh0, bh1, bh2, bh3, wh_base + off);
                    ldsm_x4_t(bl0, bl1, bl2, bl3, wl_base + off);
                    float* a0 = acc[np * 2 + 0];
                    float* a1 = acc[np * 2 + 1];
                    mma_bf16(a0, ah0, ah1, ah2, ah3, bh0, bh1);
                    mma_bf16(a0, al0, al1, al2, al3, bh0, bh1);
                    mma_bf16(a0, ah0, ah1, ah2, ah3, bl0, bl1);
                    mma_bf16(a1, ah0, ah1, ah2, ah3, bh2, bh3);
                    mma_bf16(a1, al0, al1, al2, al3, bh2, bh3);
                    mma_bf16(a1, ah0, ah1, ah2, ah3, bl2, bl3);
                }
            }
        }

        // epilogue for this n-chunk
        #pragma unroll
        for (int n = 0; n < 8; n++) {
            int c = nc + nw * 64 + n * 8 + (lane & 3) * 2;   // 0..511
            float b0v = 0.f, b1v = 0.f;
            float* d0;
            float* d1;
            if (c < 256) {
                b0v = b1[l * HH + c];
                b1v = b1[l * HH + c + 1];
                d0 = g_P + (size_t)(n0 + r0) * HH + c;
                d1 = g_P + (size_t)(n0 + r1) * HH + c;
            } else {
                d0 = g_Q + (size_t)(n0 + r0) * HH + (c - 256);
                d1 = g_Q + (size_t)(n0 + r1) * HH + (c - 256);
            }
            *(float2*)d0 = make_float2(acc[n][0] + b0v, acc[n][1] + b1v);
            *(float2*)d1 = make_float2(acc[n][2] + b0v, acc[n][3] + b1v);
        }
    }
}

// ---------------- zero S / gsum ----------------------------------------------
__global__ void zero_S_kernel()
{
    int i = blockIdx.x * blockDim.x + threadIdx.x;
    ((float4*)g_S)[i] = make_float4(0.f, 0.f, 0.f, 0.f);
}
__global__ void zero_gsum_kernel()
{
    int i = blockIdx.x * blockDim.x + threadIdx.x;
    if (i < BG * DD) g_gsum[i] = 0.f;
}

// ---------------- edge kernel: S[dst] += silu(P[src]+Q[dst]+ef@W1c) ----------
#define EPC 128   // edges per CTA

__global__ void __launch_bounds__(256) edge_kernel(
    const int* __restrict__ ei, const float* __restrict__ W1, int l)
{
    __shared__ float W1c[16 * HH];      // 16 KB
    __shared__ int   sidx[2 * EPC];     // 1 KB
    __shared__ int   sflag[EPC];        // 0.5 KB

    int t = threadIdx.x;
    int e0 = blockIdx.x * EPC;

    if (t < EPC)            sidx[t] = ei[e0 + t];
    else if (t < 2 * EPC)   sidx[t] = ei[EE + e0 + (t - EPC)];
    for (int i = t; i < EPC; i += 256) sflag[i] = g_eflag[e0 + i];
    const float* w1c_g = W1 + ((size_t)l * 272 + 256) * HH;
    for (int i = t; i < 16 * HH; i += 256) W1c[i] = w1c_g[i];
    __syncthreads();

    int eq = t >> 6;            // 0..3 (4 edges in flight)
    int k0 = (t & 63) << 2;     // 0..252 step 4

    #pragma unroll 2
    for (int eb = 0; eb < EPC; eb += 4) {
        int e = eb + eq;
        int s  = sidx[e];
        int dd = sidx[EPC + e];
        float4 z = *(const float4*)(g_P + (size_t)s * HH + k0);
        float4 q = *(const float4*)(g_Q + (size_t)dd * HH + k0);
        z.x += q.x; z.y += q.y; z.z += q.z; z.w += q.w;
        if (sflag[e]) {   // warp-uniform; rare (~8%)
            const float* efp = g_ef + (size_t)(e0 + e) * NRBF;
            #pragma unroll
            for (int j = 0; j < NRBF; j++) {
                float ev = __ldg(efp + j);
                float4 w = *(const float4*)(W1c + j * HH + k0);
                z.x += ev * w.x; z.y += ev * w.y;
                z.z += ev * w.z; z.w += ev * w.w;
            }
        }
        red_v4(g_S + (size_t)dd * HH + k0,
               silu_f(z.x), silu_f(z.y), silu_f(z.z), silu_f(z.w));
    }
}

// ---------------- fused agg+upd (tensor-core) --------------------------------
// Phase 1: agg[32][128] = S[32][256]@mW2 + deg*b2   (accumulators only)
// Phase 2: u_in = [h | agg] split into smem A
// Phase 3: hid = silu(u_in @ uW1 + b1)
// Phase 4: h += hid @ uW2 + b2
#define UP_A_LD 264
#define UP_W_LD 264
#define UP_SMEM (32 * UP_A_LD * 2 * 2 + 32 * UP_W_LD * 2 * 2)   // 67584 B

__global__ void __launch_bounds__(256) aggupd_mma_kernel(
    const float* __restrict__ mb2,
    const float* __restrict__ b1, const float* __restrict__ b2, int l)
{
    extern __shared__ char smc[];
    __nv_bfloat16* Ah = (__nv_bfloat16*)smc;                        // 32*264
    __nv_bfloat16* Al = (__nv_bfloat16*)(smc + 32 * UP_A_LD * 2);
    __nv_bfloat16* Wh = (__nv_bfloat16*)(smc + 32 * UP_A_LD * 4);
    __nv_bfloat16* Wl = (__nv_bfloat16*)(smc + 32 * UP_A_LD * 4 + 32 * UP_W_LD * 2);

    int t = threadIdx.x;
    int warp = t >> 5, lane = t & 31;
    int mw = warp & 1, nwx = warp >> 1;     // 2 m-warps x 4 n-warps
    int n0 = blockIdx.x * 32;

    uint32_t a_row = (uint32_t)(mw * 16 + (lane & 15));
    uint32_t a_kh  = (uint32_t)((lane >> 4) << 3);
    uint32_t ah_base = smem_u32(Ah), al_base = smem_u32(Al);
    uint32_t b_krow = (uint32_t)(lane & 15);
    uint32_t wh_base = smem_u32(Wh), wl_base = smem_u32(Wl);

    int r0 = mw * 16 + (lane >> 2);
    int r1 = r0 + 8;

    // ---- Phase 0: load S[32][256] -> split bf16 into A ----
    {
        const float4* sp = (const float4*)(g_S + (size_t)n0 * HH);
        #pragma unroll
        for (int j = 0; j < 8; j++) {
            int i = t + j * 256;           // 2048 float4
            int node = i >> 6;
            int k4 = (i & 63) << 2;
            float4 v = sp[i];
            uint32_t h01, l01, h23, l23;
            split2(v.x, v.y, h01, l01);
            split2(v.z, v.w, h23, l23);
            *(uint32_t*)(Ah + node * UP_A_LD + k4)     = h01;
            *(uint32_t*)(Ah + node * UP_A_LD + k4 + 2) = h23;
            *(uint32_t*)(Al + node * UP_A_LD + k4)     = l01;
            *(uint32_t*)(Al + node * UP_A_LD + k4 + 2) = l23;
        }
    }

    // ---- Phase 1: agg GEMM (S @ mW2) ----
    float acc_g[4][4];
    #pragma unroll
    for (int n = 0; n < 4; n++)
        #pragma unroll
        for (int c = 0; c < 4; c++) acc_g[n][c] = 0.f;

    {
        uint32_t b_noff = (uint32_t)(nwx * 32 + ((lane >> 4) << 3));
        const __nv_bfloat16* w2h = g_mW2h + (size_t)l * HH * DD;
        const __nv_bfloat16* w2l = g_mW2l + (size_t)l * HH * DD;

        for (int kc = 0; kc < HH; kc += 32) {
            __syncthreads();
            #pragma unroll
            for (int j = 0; j < 4; j++) {
                int i = t + j * 256;        // 1024 uint2 over [32][128]
                int kk = i >> 5;
                int n4 = (i & 31) << 2;
                *(uint2*)(Wh + kk * UP_W_LD + n4) =
                    *(const uint2*)(w2h + (size_t)(kc + kk) * DD + n4);
                *(uint2*)(Wl + kk * UP_W_LD + n4) =
                    *(const uint2*)(w2l + (size_t)(kc + kk) * DD + n4);
            }
            __syncthreads();

            #pragma unroll
            for (int ks = 0; ks < 2; ks++) {
                uint32_t k = (uint32_t)(kc + ks * 16);
                uint32_t ah0, ah1, ah2, ah3, al0, al1, al2, al3;
                ldsm_x4(ah0, ah1, ah2, ah3, ah_base + (a_row * UP_A_LD + k + a_kh) * 2);
                ldsm_x4(al0, al1, al2, al3, al_base + (a_row * UP_A_LD + k + a_kh) * 2);
                #pragma unroll
                for (int np = 0; np < 2; np++) {
                    uint32_t off = (((uint32_t)(ks * 16) + b_krow) * UP_W_LD
                                    + b_noff + (uint32_t)(np * 16)) * 2;
                    uint32_t bh0, bh1, bh2, bh3, bl0, bl1, bl2, bl3;
                    ldsm_x4_t(bh0, bh1, bh2, bh3, wh_base + off);
                    ldsm_x4_t(bl0, bl1, bl2, bl3, wl_base + off);
                    float* a0 = acc_g[np * 2 + 0];
                    float* a1 = acc_g[np * 2 + 1];
                    mma_bf16(a0, ah0, ah1, ah2, ah3, bh0, bh1);
                    mma_bf16(a0, al0, al1, al2, al3, bh0, bh1);
                    mma_bf16(a0, ah0, ah1, ah2, ah3, bl0, bl1);
                    mma_bf16(a1, ah0, ah1, ah2, ah3, bh2, bh3);
                    mma_bf16(a1, al0, al1, al2, al3, bh2, bh3);
                    mma_bf16(a1, ah0, ah1, ah2, ah3, bl2, bl3);
                }
            }
        }
    }

    // ---- Phase 2: build u_in = [h | agg] split into A ----
    __syncthreads();   // all warps done reading S from A
    {
        // agg half (cols 128..255) straight from registers
        float dg0 = g_degf[n0 + r0];
        float dg1 = g_degf[n0 + r1];
        #pragma unroll
        for (int n = 0; n < 4; n++) {
            int c = nwx * 32 + n * 8 + (lane & 3) * 2;   // 0..127
            float bb0 = mb2[l * DD + c];
            float bb1 = mb2[l * DD + c + 1];
            uint32_t hi, lo;
            split2(acc_g[n][0] + dg0 * bb0, acc_g[n][1] + dg0 * bb1, hi, lo);
            *(uint32_t*)(Ah + r0 * UP_A_LD + 128 + c) = hi;
            *(uint32_t*)(Al + r0 * UP_A_LD + 128 + c) = lo;
            split2(acc_g[n][2] + dg1 * bb0, acc_g[n][3] + dg1 * bb1, hi, lo);
            *(uint32_t*)(Ah + r1 * UP_A_LD + 128 + c) = hi;
            *(uint32_t*)(Al + r1 * UP_A_LD + 128 + c) = lo;
        }
        // h half (cols 0..127) from global
        const float4* hp = (const float4*)(g_h + (size_t)n0 * DD);
        #pragma unroll
        for (int j = 0; j < 4; j++) {
            int i = t + j * 256;           // 1024 float4
            int node = i >> 5;
            int k4 = (i & 31) << 2;
            float4 v = hp[i];
            uint32_t h01, l01, h23, l23;
            split2(v.x, v.y, h01, l01);
            split2(v.z, v.w, h23, l23);
            *(uint32_t*)(Ah + node * UP_A_LD + k4)     = h01;
            *(uint32_t*)(Ah + node * UP_A_LD + k4 + 2) = h23;
            *(uint32_t*)(Al + node * UP_A_LD + k4)     = l01;
            *(uint32_t*)(Al + node * UP_A_LD + k4 + 2) = l23;
        }
    }

    // ---- Phase 3: GEMM1: hid[32][256] = u_in @ uW1 + b1, silu ----
    float acc1[8][4];
    #pragma unroll
    for (int n = 0; n < 8; n++)
        #pragma unroll
        for (int c = 0; c < 4; c++) acc1[n][c] = 0.f;

    {
        uint32_t b_noff1 = (uint32_t)(nwx * 64 + ((lane >> 4) << 3));
        const __nv_bfloat16* w1h = g_uW1h + (size_t)l * HH * HH;
        const __nv_bfloat16* w1l = g_uW1l + (size_t)l * HH * HH;

        for (int kc = 0; kc < HH; kc += 32) {
            __syncthreads();
            #pragma unroll
            for (int j = 0; j < 8; j++) {
                int i = t + j * 256;        // 2048 uint2 over [32][256]
                int kk = i >> 6;
                int n4 = (i & 63) << 2;
                *(uint2*)(Wh + kk * UP_W_LD + n4) =
                    *(const uint2*)(w1h + (size_t)(kc + kk) * HH + n4);
                *(uint2*)(Wl + kk * UP_W_LD + n4) =
                    *(const uint2*)(w1l + (size_t)(kc + kk) * HH + n4);
            }
            __syncthreads();

            #pragma unroll
            for (int ks = 0; ks < 2; ks++) {
                uint32_t k = (uint32_t)(kc + ks * 16);
                uint32_t ah0, ah1, ah2, ah3, al0, al1, al2, al3;
                ldsm_x4(ah0, ah1, ah2, ah3, ah_base + (a_row * UP_A_LD + k + a_kh) * 2);
                ldsm_x4(al0, al1, al2, al3, al_base + (a_row * UP_A_LD + k + a_kh) * 2);
                #pragma unroll
                for (int np = 0; np < 4; np++) {
                    uint32_t off = (((uint32_t)(ks * 16) + b_krow) * UP_W_LD
                                    + b_noff1 + (uint32_t)(np * 16)) * 2;
                    uint32_t bh0, bh1, bh2, bh3, bl0, bl1, bl2, bl3;
                    ldsm_x4_t(bh0, bh1, bh2, bh3, wh_base + off);
                    ldsm_x4_t(bl0, bl1, bl2, bl3, wl_base + off);
                    float* a0 = acc1[np * 2 + 0];
                    float* a1 = acc1[np * 2 + 1];
                    mma_bf16(a0, ah0, ah1, ah2, ah3, bh0, bh1);
                    mma_bf16(a0, al0, al1, al2, al3, bh0, bh1);
                    mma_bf16(a0, ah0, ah1, ah2, ah3, bl0, bl1);
                    mma_bf16(a1, ah0, ah1, ah2, ah3, bh2, bh3);
                    mma_bf16(a1, al0, al1, al2, al3, bh2, bh3);
                    mma_bf16(a1, ah0, ah1, ah2, ah3, bl2, bl3);
                }
            }
        }
    }

    // epilogue GEMM1: silu + re-split into A buffer (hidden)
    __syncthreads();    // all warps done reading u_in from A
    #pragma unroll
    for (int n = 0; n < 8; n++) {
        int c = nwx * 64 + n * 8 + (lane & 3) * 2;
        float bb0 = b1[l * HH + c];
        float bb1 = b1[l * HH + c + 1];
        float v00 = silu_f(acc1[n][0] + bb0);
        float v01 = silu_f(acc1[n][1] + bb1);
        float v10 = silu_f(acc1[n][2] + bb0);
        float v11 = silu_f(acc1[n][3] + bb1);
        uint32_t hi, lo;
        split2(v00, v01, hi, lo);
        *(uint32_t*)(Ah + r0 * UP_A_LD + c) = hi;
        *(uint32_t*)(Al + r0 * UP_A_LD + c) = lo;
        split2(v10, v11, hi, lo);
        *(uint32_t*)(Ah + r1 * UP_A_LD + c) = hi;
        *(uint32_t*)(Al + r1 * UP_A_LD + c) = lo;
    }
    __syncthreads();

    // ---- Phase 4: GEMM2: dh[32][128] = hid @ uW2; h += dh + b2 ----
    float acc2[4][4];
    #pragma unroll
    for (int n = 0; n < 4; n++)
        #pragma unroll
        for (int c = 0; c < 4; c++) acc2[n][c] = 0.f;

    {
        uint32_t b_noff2 = (uint32_t)(nwx * 32 + ((lane >> 4) << 3));
        const __nv_bfloat16* w2h = g_uW2h + (size_t)l * HH * DD;
        const __nv_bfloat16* w2l = g_uW2l + (size_t)l * HH * DD;

        for (int kc = 0; kc < HH; kc += 32) {
            __syncthreads();
            #pragma unroll
            for (int j = 0; j < 4; j++) {
                int i = t + j * 256;        // 1024 uint2 over [32][128]
                int kk = i >> 5;
                int n4 = (i & 31) << 2;
                *(uint2*)(Wh + kk * UP_W_LD + n4) =
                    *(const uint2*)(w2h + (size_t)(kc + kk) * DD + n4);
                *(uint2*)(Wl + kk * UP_W_LD + n4) =
                    *(const uint2*)(w2l + (size_t)(kc + kk) * DD + n4);
            }
            __syncthreads();

            #pragma unroll
            for (int ks = 0; ks < 2; ks++) {
                uint32_t k = (uint32_t)(kc + ks * 16);
                uint32_t ah0, ah1, ah2, ah3, al0, al1, al2, al3;
                ldsm_x4(ah0, ah1, ah2, ah3, ah_base + (a_row * UP_A_LD + k + a_kh) * 2);
                ldsm_x4(al0, al1, al2, al3, al_base + (a_row * UP_A_LD + k + a_kh) * 2);
                #pragma unroll
                for (int np = 0; np < 2; np++) {
                    uint32_t off = (((uint32_t)(ks * 16) + b_krow) * UP_W_LD
                                    + b_noff2 + (uint32_t)(np * 16)) * 2;
                    uint32_t bh0, bh1, bh2, bh3, bl0, bl1, bl2, bl3;
                    ldsm_x4_t(bh0, bh1, bh2, bh3, wh_base + off);
                    ldsm_x4_t(bl0, bl1, bl2, bl3, wl_base + off);
                    float* a0 = acc2[np * 2 + 0];
                    float* a1 = acc2[np * 2 + 1];
                    mma_bf16(a0, ah0, ah1, ah2, ah3, bh0, bh1);
                    mma_bf16(a0, al0, al1, al2, al3, bh0, bh1);
                    mma_bf16(a0, ah0, ah1, ah2, ah3, bl0, bl1);
                    mma_bf16(a1, ah0, ah1, ah2, ah3, bh2, bh3);
                    mma_bf16(a1, al0, al1, al2, al3, bh2, bh3);
                    mma_bf16(a1, ah0, ah1, ah2, ah3, bl2, bl3);
                }
            }
        }
    }

    // epilogue: residual add into g_h
    #pragma unroll
    for (int n = 0; n < 4; n++) {
        int c = nwx * 32 + n * 8 + (lane & 3) * 2;
        float bb0 = b2[l * DD + c];
        float bb1 = b2[l * DD + c + 1];
        float* p0 = g_h + (size_t)(n0 + r0) * DD + c;
        float* p1 = g_h + (size_t)(n0 + r1) * DD + c;
        float2 o0 = *(float2*)p0;
        float2 o1 = *(float2*)p1;
        *(float2*)p0 = make_float2(o0.x + acc2[n][0] + bb0, o0.y + acc2[n][1] + bb1);
        *(float2*)p1 = make_float2(o1.x + acc2[n][2] + bb0, o1.y + acc2[n][3] + bb1);
    }
}

// ---------------- readout ----------------------------------------------------
__global__ void __launch_bounds__(128) accum_kernel(const int* __restrict__ batch)
{
    int c = threadIdx.x;
    int n0 = blockIdx.x * 64;
    int curb = batch[n0];
    float s = 0.f;
    for (int i = 0; i < 64; i++) {
        int n = n0 + i;
        int b = batch[n];
        if (b != curb) { atomicAdd(&g_gsum[curb * DD + c], s); s = 0.f; curb = b; }
        s += g_h[(size_t)n * DD + c];
    }
    atomicAdd(&g_gsum[curb * DD + c], s);
}

__global__ void __launch_bounds__(256) final_kernel(
    const int* __restrict__ batch,
    const float* __restrict__ rW1, const float* __restrict__ rb1,
    const float* __restrict__ rW2, const float* __restrict__ rb2,
    float* __restrict__ out)
{
    __shared__ int cnt[BG];
    __shared__ float gs[BG * DD];
    __shared__ float hid[BG * HH];
    int t = threadIdx.x;
    if (t < BG) cnt[t] = 0;
    __syncthreads();
    for (int i = t; i < NN; i += 256) atomicAdd(&cnt[batch[i]], 1);
    __syncthreads();
    for (int i = t; i < BG * DD; i += 256) {
        int b = i / DD;
        gs[i] = g_gsum[i] / (float)max(cnt[b], 1);
    }
    __syncthreads();
    for (int gr = 0; gr < BG; gr++) {
        float a = rb1[t];
        for (int k = 0; k < DD; k++) a += gs[gr * DD + k] * rW1[k * HH + t];
        hid[gr * HH + t] = silu_f(a);
    }
    __syncthreads();
    for (int idx = t; idx < BG * NOUT; idx += 256) {
        int gr = idx >> 6;
        int c  = idx & 63;
        float a = rb2[c];
        for (int k = 0; k < HH; k++) a += hid[gr * HH + k] * rW2[k * NOUT + c];
        out[idx] = a;
    }
}

// ---------------- launch -----------------------------------------------------
extern "C" void kernel_launch(void* const* d_in, const int* in_sizes, int n_in,
                              void* d_out, int out_size)
{
    const float* pos   = (const float*)d_in[0];
    const float* nf    = (const float*)d_in[1];
    const int*   ei    = (const int*)  d_in[2];
    const int*   batch = (const int*)  d_in[3];
    const float* eW1 = (const float*)d_in[4];
    const float* eb1 = (const float*)d_in[5];
    const float* eW2 = (const float*)d_in[6];
    const float* eb2 = (const float*)d_in[7];
    const float* mW1 = (const float*)d_in[8];
    const float* mb1 = (const float*)d_in[9];
    const float* mW2 = (const float*)d_in[10];
    const float* mb2 = (const float*)d_in[11];
    const float* uW1 = (const float*)d_in[12];
    const float* ub1 = (const float*)d_in[13];
    const float* uW2 = (const float*)d_in[14];
    const float* ub2 = (const float*)d_in[15];
    const float* rW1 = (const float*)d_in[16];
    const float* rb1 = (const float*)d_in[17];
    const float* rW2 = (const float*)d_in[18];
    const float* rb2 = (const float*)d_in[19];
    float* out = (float*)d_out;

    cudaFuncSetAttribute(pq_mma_kernel,
                         cudaFuncAttributeMaxDynamicSharedMemorySize, PQ_SMEM);
    cudaFuncSetAttribute(aggupd_mma_kernel,
                         cudaFuncAttributeMaxDynamicSharedMemorySize, UP_SMEM);

    embed_kernel<<<NN / 4, 128>>>(nf, eW1, eb1, eW2, eb2);
    rbf_kernel<<<EE / 256, 256>>>(pos, ei);
    zero_deg_kernel<<<NN / 256, 256>>>();
    deg_kernel<<<EE / 256, 256>>>(ei);
    split_wpq_kernel<<<(NL * 128 * 512 + 255) / 256, 256>>>(mW1);
    split_uw_kernel<<<(NL * HH * HH + 255) / 256, 256>>>(uW1, uW2, mW2);

    for (int l = 0; l < NL; l++) {
        pq_mma_kernel<<<NN / 64, 256, PQ_SMEM>>>(mb1, l);
        zero_S_kernel<<<NN * HH / 4 / 256, 256>>>();
        edge_kernel<<<EE / EPC, 256>>>(ei, mW1, l);
        aggupd_mma_kernel<<<NN / 32, 256, UP_SMEM>>>(mb2, ub1, ub2, l);
    }

    zero_gsum_kernel<<<4, 256>>>();
    accum_kernel<<<NN / 64, 128>>>(batch);
    final_kernel<<<1, 256>>>(batch, rW1, rb1, rW2, rb2, out);
}

// round 17
// speedup vs baseline: 1.5079x; 1.5079x over previous
#include <cuda_runtime.h>
#include <cuda_bf16.h>
#include <cstdint>

#define NN 16384
#define EE 524288
#define BG 8
#define FIN 26
#define DD 128
#define HH 256
#define NOUT 64
#define NL 4
#define NRBF 16

// ---------------- device scratch (statically allocated; no cudaMalloc) -------
__device__ float g_h[NN * DD];        // node features (residual stream)
__device__ float g_P[NN * HH];        // h @ W1a + b1
__device__ float g_Q[NN * HH];        // h @ W1b
__device__ float g_ef[EE * NRBF];     // edge RBF features (valid only if flag)
__device__ int   g_eflag[EE];         // 1 if d < cutoff (ef nonzero)
__device__ float g_S[NN * HH];        // sum of silu(z) per dst node
__device__ float g_agg[NN * DD];      // message aggregation (= S@W2 + deg*b2)
__device__ float g_degf[NN];          // per-node in-degree (float)
__device__ float g_gsum[BG * DD];     // per-graph sums
// pre-split bf16 weights (hi/lo Markidis pairs)
__device__ __nv_bfloat16 g_Wpq_h[NL * 128 * 512];  // [W1a|W1b] concat on N
__device__ __nv_bfloat16 g_Wpq_l[NL * 128 * 512];
__device__ __nv_bfloat16 g_uW1h[NL * HH * HH];
__device__ __nv_bfloat16 g_uW1l[NL * HH * HH];
__device__ __nv_bfloat16 g_uW2h[NL * HH * DD];
__device__ __nv_bfloat16 g_uW2l[NL * HH * DD];
__device__ __nv_bfloat16 g_mW2h[NL * HH * DD];
__device__ __nv_bfloat16 g_mW2l[NL * HH * DD];

__device__ __forceinline__ float silu_f(float x) {
    return x * __frcp_rn(1.f + __expf(-x));
}

__device__ __forceinline__ void red_v4(float* p, float a, float b, float c, float d) {
    asm volatile("red.global.add.v4.f32 [%0], {%1,%2,%3,%4};"
                 :: "l"(p), "f"(a), "f"(b), "f"(c), "f"(d) : "memory");
}

// ---------------- mma.sync helpers ------------------------------------------
__device__ __forceinline__ uint32_t smem_u32(const void* p) {
    return (uint32_t)__cvta_generic_to_shared(p);
}
__device__ __forceinline__ void ldsm_x4(uint32_t& r0, uint32_t& r1,
                                        uint32_t& r2, uint32_t& r3, uint32_t a) {
    asm volatile("ldmatrix.sync.aligned.m8n8.x4.shared.b16 {%0,%1,%2,%3}, [%4];"
                 : "=r"(r0), "=r"(r1), "=r"(r2), "=r"(r3) : "r"(a));
}
__device__ __forceinline__ void ldsm_x4_t(uint32_t& r0, uint32_t& r1,
                                          uint32_t& r2, uint32_t& r3, uint32_t a) {
    asm volatile("ldmatrix.sync.aligned.m8n8.x4.trans.shared.b16 {%0,%1,%2,%3}, [%4];"
                 : "=r"(r0), "=r"(r1), "=r"(r2), "=r"(r3) : "r"(a));
}
__device__ __forceinline__ void mma_bf16(float* d, uint32_t a0, uint32_t a1,
                                         uint32_t a2, uint32_t a3,
                                         uint32_t b0, uint32_t b1) {
    asm volatile(
        "mma.sync.aligned.m16n8k16.row.col.f32.bf16.bf16.f32 "
        "{%0,%1,%2,%3}, {%4,%5,%6,%7}, {%8,%9}, {%0,%1,%2,%3};"
        : "+f"(d[0]), "+f"(d[1]), "+f"(d[2]), "+f"(d[3])
        : "r"(a0), "r"(a1), "r"(a2), "r"(a3), "r"(b0), "r"(b1));
}
// pack two floats into (hi-u32, lo-u32) bf16x2 Markidis pairs
__device__ __forceinline__ void split2(float f0, float f1, uint32_t& hi, uint32_t& lo) {
    __nv_bfloat16 h0 = __float2bfloat16_rn(f0);
    __nv_bfloat16 h1 = __float2bfloat16_rn(f1);
    __nv_bfloat16 l0 = __float2bfloat16_rn(f0 - __bfloat162float(h0));
    __nv_bfloat16 l1 = __float2bfloat16_rn(f1 - __bfloat162float(h1));
    hi = (uint32_t)__bfloat16_as_ushort(h0) | ((uint32_t)__bfloat16_as_ushort(h1) << 16);
    lo = (uint32_t)__bfloat16_as_ushort(l0) | ((uint32_t)__bfloat16_as_ushort(l1) << 16);
}

// ---------------- weight pre-split kernels -----------------------------------
__global__ void __launch_bounds__(256) split_wpq_kernel(const float* __restrict__ mW1)
{
    int i = blockIdx.x * blockDim.x + threadIdx.x;
    if (i >= NL * 128 * 512) return;
    int l = i / (128 * 512);
    int r = i % (128 * 512);
    int k = r / 512, n = r % 512;
    float w = (n < 256) ? mW1[(size_t)(l * 272 + k) * HH + n]
                        : mW1[(size_t)(l * 272 + 128 + k) * HH + (n - 256)];
    __nv_bfloat16 wh = __float2bfloat16_rn(w);
    g_Wpq_h[i] = wh;
    g_Wpq_l[i] = __float2bfloat16_rn(w - __bfloat162float(wh));
}
__global__ void __launch_bounds__(256) split_uw_kernel(
    const float* __restrict__ uW1, const float* __restrict__ uW2,
    const float* __restrict__ mW2)
{
    int i = blockIdx.x * blockDim.x + threadIdx.x;
    if (i < NL * HH * HH) {
        float w = uW1[i];
        __nv_bfloat16 wh = __float2bfloat16_rn(w);
        g_uW1h[i] = wh;
        g_uW1l[i] = __float2bfloat16_rn(w - __bfloat162float(wh));
    }
    if (i < NL * HH * DD) {
        float w = uW2[i];
        __nv_bfloat16 wh = __float2bfloat16_rn(w);
        g_uW2h[i] = wh;
        g_uW2l[i] = __float2bfloat16_rn(w - __bfloat162float(wh));
        float m = mW2[i];
        __nv_bfloat16 mh = __float2bfloat16_rn(m);
        g_mW2h[i] = mh;
        g_mW2l[i] = __float2bfloat16_rn(m - __bfloat162float(mh));
    }
}

// ---------------- embedding MLP: 26 -> 128 -> silu -> 128 -------------------
__global__ void __launch_bounds__(128) embed_kernel(
    const float* __restrict__ x, const float* __restrict__ W1,
    const float* __restrict__ b1, const float* __restrict__ W2,
    const float* __restrict__ b2)
{
    __shared__ float xs[4][FIN];
    __shared__ float hid[4][DD];
    int t = threadIdx.x;
    int n0 = blockIdx.x * 4;
    for (int i = t; i < 4 * FIN; i += 128)
        xs[i / FIN][i % FIN] = x[(size_t)n0 * FIN + i];
    __syncthreads();
    float b1t = b1[t];
    #pragma unroll
    for (int nd = 0; nd < 4; nd++) {
        float acc = b1t;
        #pragma unroll
        for (int k = 0; k < FIN; k++) acc += xs[nd][k] * W1[k * DD + t];
        hid[nd][t] = silu_f(acc);
    }
    __syncthreads();
    float b2t = b2[t];
    #pragma unroll
    for (int nd = 0; nd < 4; nd++) {
        float acc = b2t;
        for (int k = 0; k < DD; k++) acc += hid[nd][k] * W2[k * DD + t];
        g_h[(size_t)(n0 + nd) * DD + t] = acc;
    }
}

// ---------------- edge RBF + cutoff flag + degree ----------------------------
__global__ void __launch_bounds__(256) rbf_kernel(
    const float* __restrict__ pos, const int* __restrict__ ei)
{
    int e = blockIdx.x * blockDim.x + threadIdx.x;
    if (e >= EE) return;
    int s  = ei[e];
    int dd = ei[EE + e];
    atomicAdd(&g_degf[dd], 1.f);
    float dx = pos[dd * 3 + 0] - pos[s * 3 + 0];
    float dy = pos[dd * 3 + 1] - pos[s * 3 + 1];
    float dz = pos[dd * 3 + 2] - pos[s * 3 + 2];
    float d = sqrtf(dx * dx + dy * dy + dz * dz + 1e-12f);
    bool in_cut = (d < 10.f);
    g_eflag[e] = in_cut ? 1 : 0;
    if (!in_cut) return;   // ef never read for these edges
    float env = 0.5f * (cosf(0.31415926535897932f * d) + 1.f);
    #pragma unroll
    for (int i = 0; i < NRBF; i++) {
        float c = (10.f / 15.f) * (float)i;
        float u = d - c;
        g_ef[(size_t)e * NRBF + i] = env * __expf(-u * u * 1.28f);
    }
}

__global__ void __launch_bounds__(256) zero_deg_kernel()
{
    int i = blockIdx.x * blockDim.x + threadIdx.x;
    if (i < NN) g_degf[i] = 0.f;
}

// ---------------- pq (tensor-core): [P|Q][64][512] = h[64][128] @ Wpq --------
#define PQ_A_LD 136
#define PQ_W_LD 136
#define PQ_SMEM (64 * PQ_A_LD * 2 * 2 + 64 * PQ_W_LD * 2 * 2)   // 69632 B

__global__ void __launch_bounds__(256) pq_mma_kernel(const float* __restrict__ b1, int l)
{
    extern __shared__ char smc[];
    __nv_bfloat16* Ah = (__nv_bfloat16*)smc;                       // 64*136
    __nv_bfloat16* Al = (__nv_bfloat16*)(smc + 64 * PQ_A_LD * 2);
    __nv_bfloat16* Wh = (__nv_bfloat16*)(smc + 64 * PQ_A_LD * 4);
    __nv_bfloat16* Wl = (__nv_bfloat16*)(smc + 64 * PQ_A_LD * 4 + 64 * PQ_W_LD * 2);

    int t = threadIdx.x;
    int warp = t >> 5, lane = t & 31;
    int mw = warp & 3, nw = warp >> 2;
    int n0 = blockIdx.x * 64;

    // load h[64][128] fp32 -> split bf16 hi/lo
    const float4* hp = (const float4*)(g_h + (size_t)n0 * DD);
    #pragma unroll
    for (int j = 0; j < 8; j++) {
        int i = t + j * 256;           // 2048 float4
        int node = i >> 5;
        int k4 = (i & 31) << 2;
        float4 v = hp[i];
        uint32_t h01, l01, h23, l23;
        split2(v.x, v.y, h01, l01);
        split2(v.z, v.w, h23, l23);
        *(uint32_t*)(Ah + node * PQ_A_LD + k4)     = h01;
        *(uint32_t*)(Ah + node * PQ_A_LD + k4 + 2) = h23;
        *(uint32_t*)(Al + node * PQ_A_LD + k4)     = l01;
        *(uint32_t*)(Al + node * PQ_A_LD + k4 + 2) = l23;
    }

    uint32_t a_row = (uint32_t)(mw * 16 + (lane & 15));
    uint32_t a_kh  = (uint32_t)((lane >> 4) << 3);
    uint32_t ah_base = smem_u32(Ah), al_base = smem_u32(Al);
    uint32_t b_krow = (uint32_t)(lane & 15);
    uint32_t b_noff = (uint32_t)(nw * 64 + ((lane >> 4) << 3));
    uint32_t wh_base = smem_u32(Wh), wl_base = smem_u32(Wl);

    const __nv_bfloat16* wpqh = g_Wpq_h + (size_t)l * 128 * 512;
    const __nv_bfloat16* wpql = g_Wpq_l + (size_t)l * 128 * 512;

    int r0 = mw * 16 + (lane >> 2);
    int r1 = r0 + 8;

    for (int nc = 0; nc < 512; nc += 128) {
        float acc[8][4];
        #pragma unroll
        for (int n = 0; n < 8; n++)
            #pragma unroll
            for (int c = 0; c < 4; c++) acc[n][c] = 0.f;

        for (int kc = 0; kc < 128; kc += 64) {
            __syncthreads();
            #pragma unroll
            for (int j = 0; j < 8; j++) {
                int i = t + j * 256;       // 2048 uint2 over [64][128]
                int kk = i >> 5;
                int n4 = (i & 31) << 2;
                *(uint2*)(Wh + kk * PQ_W_LD + n4) =
                    *(const uint2*)(wpqh + (size_t)(kc + kk) * 512 + nc + n4);
                *(uint2*)(Wl + kk * PQ_W_LD + n4) =
                    *(const uint2*)(wpql + (size_t)(kc + kk) * 512 + nc + n4);
            }
            __syncthreads();

            #pragma unroll
            for (int ks = 0; ks < 4; ks++) {
                uint32_t k = (uint32_t)(kc + ks * 16);
                uint32_t ah0, ah1, ah2, ah3, al0, al1, al2, al3;
                ldsm_x4(ah0, ah1, ah2, ah3, ah_base + (a_row * PQ_A_LD + k + a_kh) * 2);
                ldsm_x4(al0, al1, al2, al3, al_base + (a_row * PQ_A_LD + k + a_kh) * 2);
                #pragma unroll
                for (int np = 0; np < 4; np++) {
                    uint32_t off = (((uint32_t)(ks * 16) + b_krow) * PQ_W_LD
                                    + b_noff + (uint32_t)(np * 16)) * 2;
                    uint32_t bh0, bh1, bh2, bh3, bl0, bl1, bl2, bl3;
                    ldsm_x4_t(bh0, bh1, bh2, bh3, wh_base + off);
                    ldsm_x4_t(bl0, bl1, bl2, bl3, wl_base + off);
                    float* a0 = acc[np * 2 + 0];
                    float* a1 = acc[np * 2 + 1];
                    mma_bf16(a0, ah0, ah1, ah2, ah3, bh0, bh1);
                    mma_bf16(a0, al0, al1, al2, al3, bh0, bh1);
                    mma_bf16(a0, ah0, ah1, ah2, ah3, bl0, bl1);
                    mma_bf16(a1, ah0, ah1, ah2, ah3, bh2, bh3);
                    mma_bf16(a1, al0, al1, al2, al3, bh2, bh3);
                    mma_bf16(a1, ah0, ah1, ah2, ah3, bl2, bl3);
                }
            }
        }

        // epilogue for this n-chunk
        #pragma unroll
        for (int n = 0; n < 8; n++) {
            int c = nc + nw * 64 + n * 8 + (lane & 3) * 2;   // 0..511
            float b0v = 0.f, b1v = 0.f;
            float* d0;
            float* d1;
            if (c < 256) {
                b0v = b1[l * HH + c];
                b1v = b1[l * HH + c + 1];
                d0 = g_P + (size_t)(n0 + r0) * HH + c;
                d1 = g_P + (size_t)(n0 + r1) * HH + c;
            } else {
                d0 = g_Q + (size_t)(n0 + r0) * HH + (c - 256);
                d1 = g_Q + (size_t)(n0 + r1) * HH + (c - 256);
            }
            *(float2*)d0 = make_float2(acc[n][0] + b0v, acc[n][1] + b1v);
            *(float2*)d1 = make_float2(acc[n][2] + b0v, acc[n][3] + b1v);
        }
    }
}

// ---------------- zero S / gsum ----------------------------------------------
__global__ void zero_S_kernel()
{
    int i = blockIdx.x * blockDim.x + threadIdx.x;
    ((float4*)g_S)[i] = make_float4(0.f, 0.f, 0.f, 0.f);
}
__global__ void zero_gsum_kernel()
{
    int i = blockIdx.x * blockDim.x + threadIdx.x;
    if (i < BG * DD) g_gsum[i] = 0.f;
}

// ---------------- edge kernel: S[dst] += silu(P[src]+Q[dst]+ef@W1c) ----------
#define EPC 128   // edges per CTA

__global__ void __launch_bounds__(256) edge_kernel(
    const int* __restrict__ ei, const float* __restrict__ W1, int l)
{
    __shared__ float W1c[16 * HH];      // 16 KB
    __shared__ int   sidx[2 * EPC];     // 1 KB
    __shared__ int   sflag[EPC];        // 0.5 KB

    int t = threadIdx.x;
    int e0 = blockIdx.x * EPC;

    if (t < EPC)            sidx[t] = ei[e0 + t];
    else if (t < 2 * EPC)   sidx[t] = ei[EE + e0 + (t - EPC)];
    for (int i = t; i < EPC; i += 256) sflag[i] = g_eflag[e0 + i];
    const float* w1c_g = W1 + ((size_t)l * 272 + 256) * HH;
    for (int i = t; i < 16 * HH; i += 256) W1c[i] = w1c_g[i];
    __syncthreads();

    int eq = t >> 6;            // 0..3 (4 edges in flight)
    int k0 = (t & 63) << 2;     // 0..252 step 4

    #pragma unroll 2
    for (int eb = 0; eb < EPC; eb += 4) {
        int e = eb + eq;
        int s  = sidx[e];
        int dd = sidx[EPC + e];
        float4 z = *(const float4*)(g_P + (size_t)s * HH + k0);
        float4 q = *(const float4*)(g_Q + (size_t)dd * HH + k0);
        z.x += q.x; z.y += q.y; z.z += q.z; z.w += q.w;
        if (sflag[e]) {   // warp-uniform; rare (~8%)
            const float* efp = g_ef + (size_t)(e0 + e) * NRBF;
            #pragma unroll
            for (int j = 0; j < NRBF; j++) {
                float ev = __ldg(efp + j);
                float4 w = *(const float4*)(W1c + j * HH + k0);
                z.x += ev * w.x; z.y += ev * w.y;
                z.z += ev * w.z; z.w += ev * w.w;
            }
        }
        red_v4(g_S + (size_t)dd * HH + k0,
               silu_f(z.x), silu_f(z.y), silu_f(z.z), silu_f(z.w));
    }
}

// ---------------- agg (tensor-core): agg[32][128] = S[32][256]@W2 + deg*b2 ---
// Phase 0 also re-zeroes the consumed S tile for the NEXT layer's edge REDs.
#define AG_A_LD 264
#define AG_W_LD 136
#define AG_SMEM (32 * AG_A_LD * 2 * 2 + 32 * AG_W_LD * 2 * 2)   // 51200 B

__global__ void __launch_bounds__(256) agg_mma_kernel(const float* __restrict__ b2, int l)
{
    extern __shared__ char smc[];
    __nv_bfloat16* Ah = (__nv_bfloat16*)smc;                        // 32*264
    __nv_bfloat16* Al = (__nv_bfloat16*)(smc + 32 * AG_A_LD * 2);
    __nv_bfloat16* Wh = (__nv_bfloat16*)(smc + 32 * AG_A_LD * 4);
    __nv_bfloat16* Wl = (__nv_bfloat16*)(smc + 32 * AG_A_LD * 4 + 32 * AG_W_LD * 2);

    int t = threadIdx.x;
    int warp = t >> 5, lane = t & 31;
    int mw = warp & 1, nwx = warp >> 1;     // 2 m-warps x 4 n-warps
    int n0 = blockIdx.x * 32;

    // load S[32][256] fp32 -> split bf16; zero S behind us (for next layer)
    float4* sp = (float4*)(g_S + (size_t)n0 * HH);
    #pragma unroll
    for (int j = 0; j < 8; j++) {
        int i = t + j * 256;           // 2048 float4
        int node = i >> 6;
        int k4 = (i & 63) << 2;
        float4 v = sp[i];
        sp[i] = make_float4(0.f, 0.f, 0.f, 0.f);
        uint32_t h01, l01, h23, l23;
        split2(v.x, v.y, h01, l01);
        split2(v.z, v.w, h23, l23);
        *(uint32_t*)(Ah + node * AG_A_LD + k4)     = h01;
        *(uint32_t*)(Ah + node * AG_A_LD + k4 + 2) = h23;
        *(uint32_t*)(Al + node * AG_A_LD + k4)     = l01;
        *(uint32_t*)(Al + node * AG_A_LD + k4 + 2) = l23;
    }

    uint32_t a_row = (uint32_t)(mw * 16 + (lane & 15));
    uint32_t a_kh  = (uint32_t)((lane >> 4) << 3);
    uint32_t ah_base = smem_u32(Ah), al_base = smem_u32(Al);
    uint32_t b_krow = (uint32_t)(lane & 15);
    uint32_t b_noff = (uint32_t)(nwx * 32 + ((lane >> 4) << 3));
    uint32_t wh_base = smem_u32(Wh), wl_base = smem_u32(Wl);

    const __nv_bfloat16* w2h = g_mW2h + (size_t)l * HH * DD;
    const __nv_bfloat16* w2l = g_mW2l + (size_t)l * HH * DD;

    float acc[4][4];
    #pragma unroll
    for (int n = 0; n < 4; n++)
        #pragma unroll
        for (int c = 0; c < 4; c++) acc[n][c] = 0.f;

    for (int kc = 0; kc < HH; kc += 32) {
        __syncthreads();
        #pragma unroll
        for (int j = 0; j < 4; j++) {
            int i = t + j * 256;        // 1024 uint2 over [32][128]
            int kk = i >> 5;
            int n4 = (i & 31) << 2;
            *(uint2*)(Wh + kk * AG_W_LD + n4) =
                *(const uint2*)(w2h + (size_t)(kc + kk) * DD + n4);
            *(uint2*)(Wl + kk * AG_W_LD + n4) =
                *(const uint2*)(w2l + (size_t)(kc + kk) * DD + n4);
        }
        __syncthreads();

        #pragma unroll
        for (int ks = 0; ks < 2; ks++) {
            uint32_t k = (uint32_t)(kc + ks * 16);
            uint32_t ah0, ah1, ah2, ah3, al0, al1, al2, al3;
            ldsm_x4(ah0, ah1, ah2, ah3, ah_base + (a_row * AG_A_LD + k + a_kh) * 2);
            ldsm_x4(al0, al1, al2, al3, al_base + (a_row * AG_A_LD + k + a_kh) * 2);
            #pragma unroll
            for (int np = 0; np < 2; np++) {
                uint32_t off = (((uint32_t)(ks * 16) + b_krow) * AG_W_LD
                                + b_noff + (uint32_t)(np * 16)) * 2;
                uint32_t bh0, bh1, bh2, bh3, bl0, bl1, bl2, bl3;
                ldsm_x4_t(bh0, bh1, bh2, bh3, wh_base + off);
                ldsm_x4_t(bl0, bl1, bl2, bl3, wl_base + off);
                float* a0 = acc[np * 2 + 0];
                float* a1 = acc[np * 2 + 1];
                mma_bf16(a0, ah0, ah1, ah2, ah3, bh0, bh1);
                mma_bf16(a0, al0, al1, al2, al3, bh0, bh1);
                mma_bf16(a0, ah0, ah1, ah2, ah3, bl0, bl1);
                mma_bf16(a1, ah0, ah1, ah2, ah3, bh2, bh3);
                mma_bf16(a1, al0, al1, al2, al3, bh2, bh3);
                mma_bf16(a1, ah0, ah1, ah2, ah3, bl2, bl3);
            }
        }
    }

    int r0 = mw * 16 + (lane >> 2);
    int r1 = r0 + 8;
    float dg0 = g_degf[n0 + r0];
    float dg1 = g_degf[n0 + r1];
    #pragma unroll
    for (int n = 0; n < 4; n++) {
        int c = nwx * 32 + n * 8 + (lane & 3) * 2;
        float bb0 = b2[l * DD + c];
        float bb1 = b2[l * DD + c + 1];
        *(float2*)(g_agg + (size_t)(n0 + r0) * DD + c) =
            make_float2(acc[n][0] + dg0 * bb0, acc[n][1] + dg0 * bb1);
        *(float2*)(g_agg + (size_t)(n0 + r1) * DD + c) =
            make_float2(acc[n][2] + dg1 * bb0, acc[n][3] + dg1 * bb1);
    }
}

// ---------------- upd (tensor-core): [h|agg] -> 256 -> silu -> 128, resid ----
#define UP_A_LD 264
#define UP_W_LD 264
#define UP_SMEM (32 * UP_A_LD * 2 * 2 + 32 * UP_W_LD * 2 * 2)   // 67584 B

__global__ void __launch_bounds__(256) upd_mma_kernel(
    const float* __restrict__ b1, const float* __restrict__ b2, int l)
{
    extern __shared__ char smc[];
    __nv_bfloat16* Ah = (__nv_bfloat16*)smc;                        // 32*264
    __nv_bfloat16* Al = (__nv_bfloat16*)(smc + 32 * UP_A_LD * 2);
    __nv_bfloat16* Wh = (__nv_bfloat16*)(smc + 32 * UP_A_LD * 4);
    __nv_bfloat16* Wl = (__nv_bfloat16*)(smc + 32 * UP_A_LD * 4 + 32 * UP_W_LD * 2);

    int t = threadIdx.x;
    int warp = t >> 5, lane = t & 31;
    int mw = warp & 1, nwx = warp >> 1;     // 2 m-warps x 4 n-warps
    int n0 = blockIdx.x * 32;

    // load u_in = [h | agg] [32][256] fp32 -> split bf16
    {
        const float4* hp = (const float4*)(g_h + (size_t)n0 * DD);
        const float4* ap = (const float4*)(g_agg + (size_t)n0 * DD);
        #pragma unroll
        for (int j = 0; j < 4; j++) {
            int i = t + j * 256;           // 1024 float4 per source
            int node = i >> 5;
            int k4 = (i & 31) << 2;
            float4 v = hp[i];
            uint32_t h01, l01, h23, l23;
            split2(v.x, v.y, h01, l01);
            split2(v.z, v.w, h23, l23);
            *(uint32_t*)(Ah + node * UP_A_LD + k4)     = h01;
            *(uint32_t*)(Ah + node * UP_A_LD + k4 + 2) = h23;
            *(uint32_t*)(Al + node * UP_A_LD + k4)     = l01;
            *(uint32_t*)(Al + node * UP_A_LD + k4 + 2) = l23;
            float4 w = ap[i];
            split2(w.x, w.y, h01, l01);
            split2(w.z, w.w, h23, l23);
            *(uint32_t*)(Ah + node * UP_A_LD + 128 + k4)     = h01;
            *(uint32_t*)(Ah + node * UP_A_LD + 128 + k4 + 2) = h23;
            *(uint32_t*)(Al + node * UP_A_LD + 128 + k4)     = l01;
            *(uint32_t*)(Al + node * UP_A_LD + 128 + k4 + 2) = l23;
        }
    }

    uint32_t a_row = (uint32_t)(mw * 16 + (lane & 15));
    uint32_t a_kh  = (uint32_t)((lane >> 4) << 3);
    uint32_t ah_base = smem_u32(Ah), al_base = smem_u32(Al);
    uint32_t b_krow = (uint32_t)(lane & 15);
    uint32_t wh_base = smem_u32(Wh), wl_base = smem_u32(Wl);

    int r0 = mw * 16 + (lane >> 2);
    int r1 = r0 + 8;

    // ---- GEMM1: hid[32][256] = u_in @ uW1 + b1, silu ----
    float acc1[8][4];
    #pragma unroll
    for (int n = 0; n < 8; n++)
        #pragma unroll
        for (int c = 0; c < 4; c++) acc1[n][c] = 0.f;

    uint32_t b_noff1 = (uint32_t)(nwx * 64 + ((lane >> 4) << 3));
    const __nv_bfloat16* w1h = g_uW1h + (size_t)l * HH * HH;
    const __nv_bfloat16* w1l = g_uW1l + (size_t)l * HH * HH;

    for (int kc = 0; kc < HH; kc += 32) {
        __syncthreads();
        #pragma unroll
        for (int j = 0; j < 8; j++) {
            int i = t + j * 256;        // 2048 uint2 over [32][256]
            int kk = i >> 6;
            int n4 = (i & 63) << 2;
            *(uint2*)(Wh + kk * UP_W_LD + n4) =
                *(const uint2*)(w1h + (size_t)(kc + kk) * HH + n4);
            *(uint2*)(Wl + kk * UP_W_LD + n4) =
                *(const uint2*)(w1l + (size_t)(kc + kk) * HH + n4);
        }
        __syncthreads();

        #pragma unroll
        for (int ks = 0; ks < 2; ks++) {
            uint32_t k = (uint32_t)(kc + ks * 16);
            uint32_t ah0, ah1, ah2, ah3, al0, al1, al2, al3;
            ldsm_x4(ah0, ah1, ah2, ah3, ah_base + (a_row * UP_A_LD + k + a_kh) * 2);
            ldsm_x4(al0, al1, al2, al3, al_base + (a_row * UP_A_LD + k + a_kh) * 2);
            #pragma unroll
            for (int np = 0; np < 4; np++) {
                uint32_t off = (((uint32_t)(ks * 16) + b_krow) * UP_W_LD
                                + b_noff1 + (uint32_t)(np * 16)) * 2;
                uint32_t bh0, bh1, bh2, bh3, bl0, bl1, bl2, bl3;
                ldsm_x4_t(bh0, bh1, bh2, bh3, wh_base + off);
                ldsm_x4_t(bl0, bl1, bl2, bl3, wl_base + off);
                float* a0 = acc1[np * 2 + 0];
                float* a1 = acc1[np * 2 + 1];
                mma_bf16(a0, ah0, ah1, ah2, ah3, bh0, bh1);
                mma_bf16(a0, al0, al1, al2, al3, bh0, bh1);
                mma_bf16(a0, ah0, ah1, ah2, ah3, bl0, bl1);
                mma_bf16(a1, ah0, ah1, ah2, ah3, bh2, bh3);
                mma_bf16(a1, al0, al1, al2, al3, bh2, bh3);
                mma_bf16(a1, ah0, ah1, ah2, ah3, bl2, bl3);
            }
        }
    }

    // epilogue GEMM1: silu + re-split into A buffer (hidden)
    __syncthreads();    // all warps done reading u_in from A
    #pragma unroll
    for (int n = 0; n < 8; n++) {
        int c = nwx * 64 + n * 8 + (lane & 3) * 2;
        float bb0 = b1[l * HH + c];
        float bb1 = b1[l * HH + c + 1];
        float v00 = silu_f(acc1[n][0] + bb0);
        float v01 = silu_f(acc1[n][1] + bb1);
        float v10 = silu_f(acc1[n][2] + bb0);
        float v11 = silu_f(acc1[n][3] + bb1);
        uint32_t hi, lo;
        split2(v00, v01, hi, lo);
        *(uint32_t*)(Ah + r0 * UP_A_LD + c) = hi;
        *(uint32_t*)(Al + r0 * UP_A_LD + c) = lo;
        split2(v10, v11, hi, lo);
        *(uint32_t*)(Ah + r1 * UP_A_LD + c) = hi;
        *(uint32_t*)(Al + r1 * UP_A_LD + c) = lo;
    }
    __syncthreads();

    // ---- GEMM2: dh[32][128] = hid @ uW2; h += dh + b2 ----
    float acc2[4][4];
    #pragma unroll
    for (int n = 0; n < 4; n++)
        #pragma unroll
        for (int c = 0; c < 4; c++) acc2[n][c] = 0.f;

    uint32_t b_noff2 = (uint32_t)(nwx * 32 + ((lane >> 4) << 3));
    const __nv_bfloat16* w2h = g_uW2h + (size_t)l * HH * DD;
    const __nv_bfloat16* w2l = g_uW2l + (size_t)l * HH * DD;

    for (int kc = 0; kc < HH; kc += 32) {
        __syncthreads();
        #pragma unroll
        for (int j = 0; j < 4; j++) {
            int i = t + j * 256;        // 1024 uint2 over [32][128]
            int kk = i >> 5;
            int n4 = (i & 31) << 2;
            *(uint2*)(Wh + kk * UP_W_LD + n4) =
                *(const uint2*)(w2h + (size_t)(kc + kk) * DD + n4);
            *(uint2*)(Wl + kk * UP_W_LD + n4) =
                *(const uint2*)(w2l + (size_t)(kc + kk) * DD + n4);
        }
        __syncthreads();

        #pragma unroll
        for (int ks = 0; ks < 2; ks++) {
            uint32_t k = (uint32_t)(kc + ks * 16);
            uint32_t ah0, ah1, ah2, ah3, al0, al1, al2, al3;
            ldsm_x4(ah0, ah1, ah2, ah3, ah_base + (a_row * UP_A_LD + k + a_kh) * 2);
            ldsm_x4(al0, al1, al2, al3, al_base + (a_row * UP_A_LD + k + a_kh) * 2);
            #pragma unroll
            for (int np = 0; np < 2; np++) {
                uint32_t off = (((uint32_t)(ks * 16) + b_krow) * UP_W_LD
                                + b_noff2 + (uint32_t)(np * 16)) * 2;
                uint32_t bh0, bh1, bh2, bh3, bl0, bl1, bl2, bl3;
                ldsm_x4_t(bh0, bh1, bh2, bh3, wh_base + off);
                ldsm_x4_t(bl0, bl1, bl2, bl3, wl_base + off);
                float* a0 = acc2[np * 2 + 0];
                float* a1 = acc2[np * 2 + 1];
                mma_bf16(a0, ah0, ah1, ah2, ah3, bh0, bh1);
                mma_bf16(a0, al0, al1, al2, al3, bh0, bh1);
                mma_bf16(a0, ah0, ah1, ah2, ah3, bl0, bl1);
                mma_bf16(a1, ah0, ah1, ah2, ah3, bh2, bh3);
                mma_bf16(a1, al0, al1, al2, al3, bh2, bh3);
                mma_bf16(a1, ah0, ah1, ah2, ah3, bl2, bl3);
            }
        }
    }

    // epilogue: residual add into g_h
    #pragma unroll
    for (int n = 0; n < 4; n++) {
        int c = nwx * 32 + n * 8 + (lane & 3) * 2;
        float bb0 = b2[l * DD + c];
        float bb1 = b2[l * DD + c + 1];
        float* p0 = g_h + (size_t)(n0 + r0) * DD + c;
        float* p1 = g_h + (size_t)(n0 + r1) * DD + c;
        float2 o0 = *(float2*)p0;
        float2 o1 = *(float2*)p1;
        *(float2*)p0 = make_float2(o0.x + acc2[n][0] + bb0, o0.y + acc2[n][1] + bb1);
        *(float2*)p1 = make_float2(o1.x + acc2[n][2] + bb0, o1.y + acc2[n][3] + bb1);
    }
}

// ---------------- readout ----------------------------------------------------
__global__ void __launch_bounds__(128) accum_kernel(const int* __restrict__ batch)
{
    int c = threadIdx.x;
    int n0 = blockIdx.x * 64;
    int curb = batch[n0];
    float s = 0.f;
    for (int i = 0; i < 64; i++) {
        int n = n0 + i;
        int b = batch[n];
        if (b != curb) { atomicAdd(&g_gsum[curb * DD + c], s); s = 0.f; curb = b; }
        s += g_h[(size_t)n * DD + c];
    }
    atomicAdd(&g_gsum[curb * DD + c], s);
}

__global__ void __launch_bounds__(256) final_kernel(
    const int* __restrict__ batch,
    const float* __restrict__ rW1, const float* __restrict__ rb1,
    const float* __restrict__ rW2, const float* __restrict__ rb2,
    float* __restrict__ out)
{
    __shared__ int cnt[BG];
    __shared__ float gs[BG * DD];
    __shared__ float hid[BG * HH];
    int t = threadIdx.x;
    if (t < BG) cnt[t] = 0;
    __syncthreads();
    for (int i = t; i < NN; i += 256) atomicAdd(&cnt[batch[i]], 1);
    __syncthreads();
    for (int i = t; i < BG * DD; i += 256) {
        int b = i / DD;
        gs[i] = g_gsum[i] / (float)max(cnt[b], 1);
    }
    __syncthreads();
    for (int gr = 0; gr < BG; gr++) {
        float a = rb1[t];
        for (int k = 0; k < DD; k++) a += gs[gr * DD + k] * rW1[k * HH + t];
        hid[gr * HH + t] = silu_f(a);
    }
    __syncthreads();
    for (int idx = t; idx < BG * NOUT; idx += 256) {
        int gr = idx >> 6;
        int c  = idx & 63;
        float a = rb2[c];
        for (int k = 0; k < HH; k++) a += hid[gr * HH + k] * rW2[k * NOUT + c];
        out[idx] = a;
    }
}

// ---------------- launch -----------------------------------------------------
extern "C" void kernel_launch(void* const* d_in, const int* in_sizes, int n_in,
                              void* d_out, int out_size)
{
    const float* pos   = (const float*)d_in[0];
    const float* nf    = (const float*)d_in[1];
    const int*   ei    = (const int*)  d_in[2];
    const int*   batch = (const int*)  d_in[3];
    const float* eW1 = (const float*)d_in[4];
    const float* eb1 = (const float*)d_in[5];
    const float* eW2 = (const float*)d_in[6];
    const float* eb2 = (const float*)d_in[7];
    const float* mW1 = (const float*)d_in[8];
    const float* mb1 = (const float*)d_in[9];
    const float* mW2 = (const float*)d_in[10];
    const float* mb2 = (const float*)d_in[11];
    const float* uW1 = (const float*)d_in[12];
    const float* ub1 = (const float*)d_in[13];
    const float* uW2 = (const float*)d_in[14];
    const float* ub2 = (const float*)d_in[15];
    const float* rW1 = (const float*)d_in[16];
    const float* rb1 = (const float*)d_in[17];
    const float* rW2 = (const float*)d_in[18];
    const float* rb2 = (const float*)d_in[19];
    float* out = (float*)d_out;

    cudaFuncSetAttribute(pq_mma_kernel,
                         cudaFuncAttributeMaxDynamicSharedMemorySize, PQ_SMEM);
    cudaFuncSetAttribute(agg_mma_kernel,
                         cudaFuncAttributeMaxDynamicSharedMemorySize, AG_SMEM);
    cudaFuncSetAttribute(upd_mma_kernel,
                         cudaFuncAttributeMaxDynamicSharedMemorySize, UP_SMEM);

    embed_kernel<<<NN / 4, 128>>>(nf, eW1, eb1, eW2, eb2);
    zero_deg_kernel<<<NN / 256, 256>>>();
    rbf_kernel<<<EE / 256, 256>>>(pos, ei);
    split_wpq_kernel<<<(NL * 128 * 512 + 255) / 256, 256>>>(mW1);
    split_uw_kernel<<<(NL * HH * HH + 255) / 256, 256>>>(uW1, uW2, mW2);
    zero_S_kernel<<<NN * HH / 4 / 256, 256>>>();   // layer 0; later layers zeroed by agg

    for (int l = 0; l < NL; l++) {
        pq_mma_kernel<<<NN / 64, 256, PQ_SMEM>>>(mb1, l);
        edge_kernel<<<EE / EPC, 256>>>(ei, mW1, l);
        agg_mma_kernel<<<NN / 32, 256, AG_SMEM>>>(mb2, l);
        upd_mma_kernel<<<NN / 32, 256, UP_SMEM>>>(ub1, ub2, l);
    }

    zero_gsum_kernel<<<4, 256>>>();
    accum_kernel<<<NN / 64, 128>>>(batch);
    final_kernel<<<1, 256>>>(batch, rW1, rb1, rW2, rb2, out);
}